// round 5
// baseline (speedup 1.0000x reference)
#include <cuda_runtime.h>

// ---------------------------------------------------------------------------
// SSIM (16,3,512,512) fp32, 11x11 Gaussian (sigma=1.5), zero pad, global mean.
// Separable conv; horizontal 11-tap from WARP-PRIVATE SMEM halo segments
// (only __syncwarp in main loop); vertical 11-tap via static mod-11 register
// ring (zero shifts). NEW: packed fp32x2 math (fma.rn.f32x2 / mul.rn.f32x2,
// sm_103a FFMA2) — img1/img2 share weights, so (x|y) and (x^2|y^2) pipelines
// run 2-wide, cutting FMA issue count ~40%.
// ---------------------------------------------------------------------------

#define IMW     512
#define IMH     512
#define NT      512                 // one thread per column
#define TH      171                 // output rows per band (3 bands cover 512)
#define NBANDS  3
#define NPLANES 48                  // 16 * 3
#define NBLOCKS (NPLANES * NBANDS)  // 144 CTAs -> single wave
#define SSIM_C1 0.0001f
#define SSIM_C2 0.0009f

typedef unsigned long long ull;

#define PACK2(d, lo, hi) \
    asm("mov.b64 %0, {%1, %2};" : "=l"(d) : "f"(lo), "f"(hi))
#define UNPACK2(lo, hi, s) \
    asm("mov.b64 {%0, %1}, %2;" : "=f"(lo), "=f"(hi) : "l"(s))
#define FMA2(acc, a, b) \
    asm("fma.rn.f32x2 %0, %1, %2, %0;" : "+l"(acc) : "l"(a), "l"(b))
#define MUL2(d, a, b) \
    asm("mul.rn.f32x2 %0, %1, %2;" : "=l"(d) : "l"(a), "l"(b))

__device__ float        g_partials[NBLOCKS];
__device__ unsigned int g_count;    // zero-init; reset by last block each run

// One row-phase. P must be a compile-time constant == ir mod 11.
#define PHASE(P, IRV) do {                                                    \
    const int ir_ = (IRV);                                                    \
    if (ir_ < nrows) {                                                        \
        if (ir_ + 2 < nrows) LOADR(ir_ + 2, (ir_) & 1);                       \
        {                                                                     \
            const float2* sp = &seg[(ir_) & 1][w][l];                         \
            ull hv = 0, hq = 0;            /* (hx|hy), (hxx|hyy) */           \
            float hxy = 0.f;                                                  \
            _Pragma("unroll")                                                 \
            for (int k = 0; k < 11; ++k) {                                    \
                const float2 v = sp[k];                                       \
                ull pv; PACK2(pv, v.x, v.y);                                  \
                FMA2(hv, pv, W2[k]);                                          \
                ull sq; MUL2(sq, pv, pv);                                     \
                FMA2(hq, sq, W2[k]);                                          \
                hxy += W[k] * (v.x * v.y);                                    \
            }                                                                 \
            _Pragma("unroll")                                                 \
            for (int s = 0; s < 11; ++s) {                                    \
                const int d = ((P) - s + 11) % 11;  /* compile-time */        \
                FMA2(B01[s], hv, W2[d]);                                      \
                FMA2(B23[s], hq, W2[d]);                                      \
                A4[s] += W[d] * hxy;                                          \
            }                                                                 \
            const int e_ = ((P) + 1) % 11;          /* compile-time */        \
            if (ir_ >= 10) {        /* output row m = ir-10 is real */        \
                float mu1, mu2, exx, eyy;                                     \
                UNPACK2(mu1, mu2, B01[e_]);                                   \
                UNPACK2(exx, eyy, B23[e_]);                                   \
                const float m11 = mu1 * mu1;                                  \
                const float m22 = mu2 * mu2;                                  \
                const float m12 = mu1 * mu2;                                  \
                const float s1  = exx - m11;                                  \
                const float s2  = eyy - m22;                                  \
                const float s12 = A4[e_] - m12;                               \
                const float num = (2.f*m12 + SSIM_C1) * (2.f*s12 + SSIM_C2);  \
                const float den = (m11 + m22 + SSIM_C1) * (s1 + s2 + SSIM_C2);\
                ssum += __fdividef(num, den);                                 \
            }                                                                 \
            B01[e_] = 0ULL; B23[e_] = 0ULL; A4[e_] = 0.f;                     \
            if (ir_ + 1 < nrows) STAGER((ir_ + 1) & 1, (ir_ + 1) & 1);        \
            __syncwarp();                                                     \
        }                                                                     \
    }                                                                         \
} while (0)

__global__ void __launch_bounds__(NT, 1)
ssim_main(const float* __restrict__ img1, const float* __restrict__ img2,
          float* __restrict__ out)
{
    // Normalized 1D Gaussian, sigma=1.5, 11 taps (compile-time immediates)
    const float W[11] = {
        0.00102838f, 0.00759874f, 0.03600077f, 0.10936069f, 0.21300553f,
        0.26601180f,
        0.21300553f, 0.10936069f, 0.03600077f, 0.00759874f, 0.00102838f
    };
    // Duplicated 64-bit weight pairs (w|w) for f32x2 ops (constant-folded)
    ull W2[11];
#pragma unroll
    for (int k = 0; k < 11; ++k) {
        const unsigned u = __float_as_uint(W[k]);
        W2[k] = ((ull)u << 32) | (ull)u;
    }

    const int band  = blockIdx.x;           // 0..2
    const int plane = blockIdx.y;           // 0..47
    const int t     = threadIdx.x;          // column 0..511
    const int l     = t & 31;               // lane
    const int w     = t >> 5;               // warp
    const int r0    = band * TH;
    const int rows  = (IMH - r0 < TH) ? (IMH - r0) : TH;   // 171/171/170
    const int nrows = rows + 10;
    const int pbase = plane * (IMW * IMH);

    // Warp-private double-buffered halo segments.
    // seg[buf][w][j], j in [0,42): (x,y) of image column 32*w - 5 + j.
    __shared__ float2 seg[2][16][44];

    // Static ring: slot s holds partials for output rows m with m % 11 == s.
    // B01 = (mu1|mu2) partials, B23 = (E[x^2]|E[y^2]) partials, A4 = E[xy].
    ull   B01[11], B23[11];
    float A4[11];
#pragma unroll
    for (int j = 0; j < 11; ++j) { B01[j] = 0ULL; B23[j] = 0ULL; A4[j] = 0.f; }

    // Column mapping (identical for every row):
    //   staged j = l      <-> col t - 5   (valid iff t >= 5)
    //   staged j = 32 + l <-> col t + 27  (staged iff l < 10, valid iff < 512)
    const int  c1   = t - 5;
    const bool c1ok = (t >= 5);
    const int  c2   = t + 27;
    const bool c2st = (l < 10);
    const bool c2ok = c2st && (c2 < IMW);

    float px0[2], py0[2], px1[2], py1[2];    // prefetch regs, parity = row & 1

    auto LOADR = [&](int ir, int s) {
        const int gr = r0 - 5 + ir;          // global row (zero pad if OOB)
        float a = 0.f, b = 0.f, c = 0.f, d = 0.f;
        if ((unsigned)gr < (unsigned)IMH) {
            const float* p1 = img1 + pbase + gr * IMW;
            const float* p2 = img2 + pbase + gr * IMW;
            if (c1ok) { a = __ldg(p1 + c1); b = __ldg(p2 + c1); }
            if (c2ok) { c = __ldg(p1 + c2); d = __ldg(p2 + c2); }
        }
        px0[s] = a; py0[s] = b; px1[s] = c; py1[s] = d;
    };
    auto STAGER = [&](int s, int b) {
        seg[b][w][l] = make_float2(px0[s], py0[s]);
        if (c2st) seg[b][w][32 + l] = make_float2(px1[s], py1[s]);
    };

    // Prologue: rows 0,1 in flight; row 0 staged. (row r lives in set r & 1)
    LOADR(0, 0);
    LOADR(1, 1);
    STAGER(0, 0);
    __syncwarp();

    float ssum = 0.f;

    // Uniform phases; base multiple of 11 so (base+q) % 11 == q.
    for (int base = 0; base < nrows; base += 11) {
#pragma unroll
        for (int q = 0; q < 11; ++q) {
            PHASE(q, base + q);
        }
    }

    // ---- deterministic block reduction ----
    __syncthreads();
#pragma unroll
    for (int off = 16; off; off >>= 1)
        ssum += __shfl_xor_sync(0xffffffffu, ssum, off);

    __shared__ float wsum[16];
    __shared__ bool  islast;
    if (l == 0) wsum[w] = ssum;
    __syncthreads();
    if (t == 0) {
        float v = 0.f;
#pragma unroll
        for (int i = 0; i < 16; ++i) v += wsum[i];
        g_partials[plane * NBANDS + band] = v;
        __threadfence();
        const unsigned n = atomicAdd(&g_count, 1u);
        islast = (n == (unsigned)(NBLOCKS - 1));
    }
    __syncthreads();

    // ---- last CTA: fixed-order (deterministic) final reduction ----
    if (islast) {
        __threadfence();
        float v = (t < NBLOCKS) ? g_partials[t] : 0.f;
#pragma unroll
        for (int off = 16; off; off >>= 1)
            v += __shfl_xor_sync(0xffffffffu, v, off);
        if (l == 0) wsum[w] = v;
        __syncthreads();
        if (t == 0) {
            float s = 0.f;
#pragma unroll
            for (int i = 0; i < 16; ++i) s += wsum[i];
            out[0] = s * (1.0f / 12582912.0f);  // / (16*3*512*512)
            g_count = 0u;                        // reset for next graph replay
        }
    }
}

extern "C" void kernel_launch(void* const* d_in, const int* in_sizes, int n_in,
                              void* d_out, int out_size)
{
    const float* img1 = (const float*)d_in[0];
    const float* img2 = (const float*)d_in[1];
    (void)in_sizes; (void)n_in; (void)out_size;

    dim3 grid(NBANDS, NPLANES);
    ssim_main<<<grid, NT>>>(img1, img2, (float*)d_out);
}

// round 6
// speedup vs baseline: 1.6855x; 1.6855x over previous
#include <cuda_runtime.h>

// ---------------------------------------------------------------------------
// SSIM (16,3,512,512) fp32, 11x11 Gaussian (sigma=1.5), zero pad, global mean.
// Separable conv; horizontal 11-tap from WARP-PRIVATE SMEM halo segments;
// vertical 11-tap via static mod-11 register ring (zero shifts).
// NEW: cp.async (LDGSTS) GMEM->SMEM pipeline, depth 3 (issue row p+3 at
// phase p, wait_group(2) guarantees row p complete) over 8 rotating buffers.
// Removes the LDG-scoreboard stall on the old per-phase STS (~577-cyc DRAM
// latency vs ~330-cyc phase) and frees the prefetch registers.
// ---------------------------------------------------------------------------

#define IMW     512
#define IMH     512
#define NT      512                 // one thread per column
#define TH      171                 // output rows per band (3 bands cover 512)
#define NBANDS  3
#define NPLANES 48                  // 16 * 3
#define NBLOCKS (NPLANES * NBANDS)  // 144 CTAs -> single wave
#define SSIM_C1 0.0001f
#define SSIM_C2 0.0009f

__device__ float        g_partials[NBLOCKS];
__device__ unsigned int g_count;    // zero-init; reset by last block each run

#define CPA4(daddr, sptr) \
    asm volatile("cp.async.ca.shared.global [%0], [%1], 4;" \
                 :: "r"(daddr), "l"(sptr))
#define CPA_COMMIT() asm volatile("cp.async.commit_group;" ::: "memory")
#define CPA_WAIT2()  asm volatile("cp.async.wait_group 2;"  ::: "memory")

// One row-phase. P must be a compile-time constant == ir mod 11.
#define PHASE(P, IRV) do {                                                    \
    const int ir_ = (IRV);                                                    \
    if (ir_ < nrows) {                                                        \
        CPA_WAIT2();               /* row ir_ (issued 3 phases ago) done */   \
        FILLROW(ir_ + 3);          /* async fill into buf[(ir_+3)&7] */       \
        CPA_COMMIT();              /* unconditional: uniform group count */   \
        __syncwarp();                                                         \
        {                                                                     \
            const float* xr = &sx[ir_ & 7][w][l];                             \
            const float* yr = &sy[ir_ & 7][w][l];                             \
            float hx = 0.f, hy = 0.f, hxx = 0.f, hyy = 0.f, hxy = 0.f;        \
            _Pragma("unroll")                                                 \
            for (int k = 0; k < 11; ++k) {                                    \
                const float xv = xr[k];                                       \
                const float yv = yr[k];                                       \
                hx  += W[k] * xv;                                             \
                hy  += W[k] * yv;                                             \
                hxx += W[k] * (xv * xv);                                      \
                hyy += W[k] * (yv * yv);                                      \
                hxy += W[k] * (xv * yv);                                      \
            }                                                                 \
            _Pragma("unroll")                                                 \
            for (int s = 0; s < 11; ++s) {                                    \
                const int d = ((P) - s + 11) % 11;  /* compile-time */        \
                const float wd = W[d];                                        \
                A0[s] += wd * hx;  A1[s] += wd * hy;                          \
                A2[s] += wd * hxx; A3[s] += wd * hyy; A4[s] += wd * hxy;      \
            }                                                                 \
            const int e_ = ((P) + 1) % 11;          /* compile-time */        \
            if (ir_ >= 10) {        /* output row m = ir-10 is real */        \
                const float mu1 = A0[e_], mu2 = A1[e_];                       \
                const float m11 = mu1 * mu1;                                  \
                const float m22 = mu2 * mu2;                                  \
                const float m12 = mu1 * mu2;                                  \
                const float s1  = A2[e_] - m11;                               \
                const float s2  = A3[e_] - m22;                               \
                const float s12 = A4[e_] - m12;                               \
                const float num = (2.f*m12 + SSIM_C1) * (2.f*s12 + SSIM_C2);  \
                const float den = (m11 + m22 + SSIM_C1) * (s1 + s2 + SSIM_C2);\
                ssum += __fdividef(num, den);                                 \
            }                                                                 \
            A0[e_] = 0.f; A1[e_] = 0.f; A2[e_] = 0.f;                         \
            A3[e_] = 0.f; A4[e_] = 0.f;                                       \
        }                                                                     \
    }                                                                         \
} while (0)

__global__ void __launch_bounds__(NT, 1)
ssim_main(const float* __restrict__ img1, const float* __restrict__ img2,
          float* __restrict__ out)
{
    // Normalized 1D Gaussian, sigma=1.5, 11 taps (compile-time immediates)
    const float W[11] = {
        0.00102838f, 0.00759874f, 0.03600077f, 0.10936069f, 0.21300553f,
        0.26601180f,
        0.21300553f, 0.10936069f, 0.03600077f, 0.00759874f, 0.00102838f
    };

    const int band  = blockIdx.x;           // 0..2
    const int plane = blockIdx.y;           // 0..47
    const int t     = threadIdx.x;          // column 0..511
    const int l     = t & 31;               // lane
    const int w     = t >> 5;               // warp
    const int r0    = band * TH;
    const int rows  = (IMH - r0 < TH) ? (IMH - r0) : TH;   // 171/171/170
    const int nrows = rows + 10;
    const int pbase = plane * (IMW * IMH);

    // Warp-private 8-deep rotating halo segments.
    // sx[buf][w][j], j in [0,42): x at image column 32*w - 5 + j. Same for sy.
    __shared__ float sx[8][16][44];
    __shared__ float sy[8][16][44];

    // Static ring: slot s holds partials for output rows m with m % 11 == s.
    float A0[11], A1[11], A2[11], A3[11], A4[11];
#pragma unroll
    for (int j = 0; j < 11; ++j) {
        A0[j] = 0.f; A1[j] = 0.f; A2[j] = 0.f; A3[j] = 0.f; A4[j] = 0.f;
    }

    // Column mapping (identical for every row):
    //   slot j = l      <-> col t - 5   (valid iff t >= 5)
    //   slot j = 32 + l <-> col t + 27  (exists iff l < 10, valid iff < 512)
    const int  c1     = t - 5;
    const bool mainok = (t >= 5);
    const int  c2     = t + 27;
    const bool tailst = (l < 10);
    const bool tailok = tailst && (c2 < IMW);

    // u32 shared addresses for cp.async destinations (this warp's row 0 slot)
    unsigned sxu, syu;
    asm("{ .reg .u64 tt; cvta.to.shared.u64 tt, %1; cvt.u32.u64 %0, tt; }"
        : "=r"(sxu) : "l"(&sx[0][w][l]));
    asm("{ .reg .u64 tt; cvta.to.shared.u64 tt, %1; cvt.u32.u64 %0, tt; }"
        : "=r"(syu) : "l"(&sy[0][w][l]));
    const unsigned BSTRIDE = 16u * 44u * 4u;   // bytes per buffer

    auto FILLROW = [&](int rn) {
        if (rn < nrows) {
            const int gr = r0 - 5 + rn;         // global row (zero pad if OOB)
            const int b  = rn & 7;
            if ((unsigned)gr < (unsigned)IMH) {
                const float* p1 = img1 + pbase + gr * IMW;
                const float* p2 = img2 + pbase + gr * IMW;
                if (mainok) { CPA4(sxu + b * BSTRIDE, p1 + c1);
                              CPA4(syu + b * BSTRIDE, p2 + c1); }
                if (tailok) { CPA4(sxu + b * BSTRIDE + 128u, p1 + c2);
                              CPA4(syu + b * BSTRIDE + 128u, p2 + c2); }
            } else {
                if (mainok) { sx[b][w][l] = 0.f;      sy[b][w][l] = 0.f; }
                if (tailst) { sx[b][w][32 + l] = 0.f; sy[b][w][32 + l] = 0.f; }
            }
        }
    };

    // Pre-zero slots never written by cp.async (col-invalid); all 8 buffers.
#pragma unroll
    for (int b = 0; b < 8; ++b) {
        if (!mainok)           { sx[b][w][l] = 0.f;      sy[b][w][l] = 0.f; }
        if (tailst && !tailok) { sx[b][w][32 + l] = 0.f; sy[b][w][32 + l] = 0.f; }
    }

    // Prologue: rows 0,1,2 in flight as three groups.
    FILLROW(0); CPA_COMMIT();
    FILLROW(1); CPA_COMMIT();
    FILLROW(2); CPA_COMMIT();
    __syncwarp();

    float ssum = 0.f;

    // Uniform phases; base multiple of 11 so (base+q) % 11 == q.
    for (int base = 0; base < nrows; base += 11) {
#pragma unroll
        for (int q = 0; q < 11; ++q) {
            PHASE(q, base + q);
        }
    }

    // ---- deterministic block reduction ----
    __syncthreads();
#pragma unroll
    for (int off = 16; off; off >>= 1)
        ssum += __shfl_xor_sync(0xffffffffu, ssum, off);

    __shared__ float wsum[16];
    __shared__ bool  islast;
    if (l == 0) wsum[w] = ssum;
    __syncthreads();
    if (t == 0) {
        float v = 0.f;
#pragma unroll
        for (int i = 0; i < 16; ++i) v += wsum[i];
        g_partials[plane * NBANDS + band] = v;
        __threadfence();
        const unsigned n = atomicAdd(&g_count, 1u);
        islast = (n == (unsigned)(NBLOCKS - 1));
    }
    __syncthreads();

    // ---- last CTA: fixed-order (deterministic) final reduction ----
    if (islast) {
        __threadfence();
        float v = (t < NBLOCKS) ? g_partials[t] : 0.f;
#pragma unroll
        for (int off = 16; off; off >>= 1)
            v += __shfl_xor_sync(0xffffffffu, v, off);
        if (l == 0) wsum[w] = v;
        __syncthreads();
        if (t == 0) {
            float s = 0.f;
#pragma unroll
            for (int i = 0; i < 16; ++i) s += wsum[i];
            out[0] = s * (1.0f / 12582912.0f);  // / (16*3*512*512)
            g_count = 0u;                        // reset for next graph replay
        }
    }
}

extern "C" void kernel_launch(void* const* d_in, const int* in_sizes, int n_in,
                              void* d_out, int out_size)
{
    const float* img1 = (const float*)d_in[0];
    const float* img2 = (const float*)d_in[1];
    (void)in_sizes; (void)n_in; (void)out_size;

    dim3 grid(NBANDS, NPLANES);
    ssim_main<<<grid, NT>>>(img1, img2, (float*)d_out);
}

// round 7
// speedup vs baseline: 2.0845x; 1.2367x over previous
#include <cuda_runtime.h>

// ---------------------------------------------------------------------------
// SSIM (16,3,512,512) fp32, 11x11 Gaussian (sigma=1.5), zero pad, global mean.
// Separable conv; horizontal 11-tap from WARP-PRIVATE SMEM halo segments;
// vertical 11-tap via static mod-11 register ring (zero shifts).
// cp.async GMEM->SMEM pipeline depth 3 over 8 rotating buffers.
// NEW: float2-interleaved staging (11 LDS.64 instead of 22 LDS.32) and
// symmetric-window pairing of the quadratic horizontal sums
// (W[k]==W[10-k] => x2/y2/xy pairs cost 3 ops instead of 4).
// ---------------------------------------------------------------------------

#define IMW     512
#define IMH     512
#define NT      512                 // one thread per column
#define TH      171                 // output rows per band (3 bands cover 512)
#define NBANDS  3
#define NPLANES 48                  // 16 * 3
#define NBLOCKS (NPLANES * NBANDS)  // 144 CTAs -> single wave
#define SSIM_C1 0.0001f
#define SSIM_C2 0.0009f

__device__ float        g_partials[NBLOCKS];
__device__ unsigned int g_count;    // zero-init; reset by last block each run

#define CPA4(daddr, sptr) \
    asm volatile("cp.async.ca.shared.global [%0], [%1], 4;" \
                 :: "r"(daddr), "l"(sptr))
#define CPA_COMMIT() asm volatile("cp.async.commit_group;" ::: "memory")
#define CPA_WAIT2()  asm volatile("cp.async.wait_group 2;"  ::: "memory")

// One row-phase. P must be a compile-time constant == ir mod 11.
#define PHASE(P, IRV) do {                                                    \
    const int ir_ = (IRV);                                                    \
    if (ir_ < nrows) {                                                        \
        CPA_WAIT2();               /* row ir_ (issued 3 phases ago) done */   \
        FILLROW(ir_ + 3);          /* async fill into buf[(ir_+3)&7] */       \
        CPA_COMMIT();              /* unconditional: uniform group count */   \
        __syncwarp();                                                         \
        {                                                                     \
            const float2* sp = &seg[ir_ & 7][w][l];                           \
            float hx, hy, hxx, hyy, hxy;                                      \
            {   /* center tap */                                              \
                const float2 c = sp[5];                                       \
                hx  = W[5] * c.x;                                             \
                hy  = W[5] * c.y;                                             \
                hxx = W[5] * (c.x * c.x);                                     \
                hyy = W[5] * (c.y * c.y);                                     \
                hxy = W[5] * (c.x * c.y);                                     \
            }                                                                 \
            _Pragma("unroll")                                                 \
            for (int k = 0; k < 5; ++k) {   /* symmetric pairs (k, 10-k) */   \
                const float2 a = sp[k];                                       \
                const float2 b = sp[10 - k];                                  \
                hx  += W[k] * (a.x + b.x);                                    \
                hy  += W[k] * (a.y + b.y);                                    \
                const float xx = a.x * a.x + b.x * b.x;                       \
                const float yy = a.y * a.y + b.y * b.y;                       \
                const float xy = a.x * a.y + b.x * b.y;                       \
                hxx += W[k] * xx;                                             \
                hyy += W[k] * yy;                                             \
                hxy += W[k] * xy;                                             \
            }                                                                 \
            _Pragma("unroll")                                                 \
            for (int s = 0; s < 11; ++s) {                                    \
                const int d = ((P) - s + 11) % 11;  /* compile-time */        \
                const float wd = W[d];                                        \
                A0[s] += wd * hx;  A1[s] += wd * hy;                          \
                A2[s] += wd * hxx; A3[s] += wd * hyy; A4[s] += wd * hxy;      \
            }                                                                 \
            const int e_ = ((P) + 1) % 11;          /* compile-time */        \
            if (ir_ >= 10) {        /* output row m = ir-10 is real */        \
                const float mu1 = A0[e_], mu2 = A1[e_];                       \
                const float m11 = mu1 * mu1;                                  \
                const float m22 = mu2 * mu2;                                  \
                const float m12 = mu1 * mu2;                                  \
                const float s1  = A2[e_] - m11;                               \
                const float s2  = A3[e_] - m22;                               \
                const float s12 = A4[e_] - m12;                               \
                const float num = (2.f*m12 + SSIM_C1) * (2.f*s12 + SSIM_C2);  \
                const float den = (m11 + m22 + SSIM_C1) * (s1 + s2 + SSIM_C2);\
                ssum += __fdividef(num, den);                                 \
            }                                                                 \
            A0[e_] = 0.f; A1[e_] = 0.f; A2[e_] = 0.f;                         \
            A3[e_] = 0.f; A4[e_] = 0.f;                                       \
        }                                                                     \
    }                                                                         \
} while (0)

__global__ void __launch_bounds__(NT, 1)
ssim_main(const float* __restrict__ img1, const float* __restrict__ img2,
          float* __restrict__ out)
{
    // Normalized 1D Gaussian, sigma=1.5, 11 taps (compile-time immediates)
    const float W[11] = {
        0.00102838f, 0.00759874f, 0.03600077f, 0.10936069f, 0.21300553f,
        0.26601180f,
        0.21300553f, 0.10936069f, 0.03600077f, 0.00759874f, 0.00102838f
    };

    const int band  = blockIdx.x;           // 0..2
    const int plane = blockIdx.y;           // 0..47
    const int t     = threadIdx.x;          // column 0..511
    const int l     = t & 31;               // lane
    const int w     = t >> 5;               // warp
    const int r0    = band * TH;
    const int rows  = (IMH - r0 < TH) ? (IMH - r0) : TH;   // 171/171/170
    const int nrows = rows + 10;
    const int pbase = plane * (IMW * IMH);

    // Warp-private 8-deep rotating halo segments, float2 = (img1, img2).
    // seg[buf][w][j], j in [0,42): pixel pair at image column 32*w - 5 + j.
    __shared__ float2 seg[8][16][44];

    // Static ring: slot s holds partials for output rows m with m % 11 == s.
    float A0[11], A1[11], A2[11], A3[11], A4[11];
#pragma unroll
    for (int j = 0; j < 11; ++j) {
        A0[j] = 0.f; A1[j] = 0.f; A2[j] = 0.f; A3[j] = 0.f; A4[j] = 0.f;
    }

    // Column mapping (identical for every row):
    //   slot j = l      <-> col t - 5   (valid iff t >= 5)
    //   slot j = 32 + l <-> col t + 27  (exists iff l < 10, valid iff < 512)
    const int  c1     = t - 5;
    const bool mainok = (t >= 5);
    const int  c2     = t + 27;
    const bool tailst = (l < 10);
    const bool tailok = tailst && (c2 < IMW);

    // u32 shared address of this warp+lane's slot in buffer 0
    unsigned sbu;
    asm("{ .reg .u64 tt; cvta.to.shared.u64 tt, %1; cvt.u32.u64 %0, tt; }"
        : "=r"(sbu) : "l"(&seg[0][w][l]));
    const unsigned BSTRIDE = 16u * 44u * 8u;   // bytes per buffer (5632)
    const unsigned TAILOFF = 32u * 8u;         // slot (32+l) - slot l (256 B)

    auto FILLROW = [&](int rn) {
        if (rn < nrows) {
            const int gr = r0 - 5 + rn;         // global row (zero pad if OOB)
            const int b  = rn & 7;
            const unsigned d = sbu + (unsigned)b * BSTRIDE;
            if ((unsigned)gr < (unsigned)IMH) {
                const float* p1 = img1 + pbase + gr * IMW;
                const float* p2 = img2 + pbase + gr * IMW;
                if (mainok) { CPA4(d, p1 + c1);               // x
                              CPA4(d + 4u, p2 + c1); }        // y
                if (tailok) { CPA4(d + TAILOFF, p1 + c2);
                              CPA4(d + TAILOFF + 4u, p2 + c2); }
            } else {
                if (mainok) seg[b][w][l]      = make_float2(0.f, 0.f);
                if (tailst) seg[b][w][32 + l] = make_float2(0.f, 0.f);
            }
        }
    };

    // Pre-zero slots never written by cp.async (col-invalid); all 8 buffers.
#pragma unroll
    for (int b = 0; b < 8; ++b) {
        if (!mainok)           seg[b][w][l]      = make_float2(0.f, 0.f);
        if (tailst && !tailok) seg[b][w][32 + l] = make_float2(0.f, 0.f);
    }

    // Prologue: rows 0,1,2 in flight as three groups.
    FILLROW(0); CPA_COMMIT();
    FILLROW(1); CPA_COMMIT();
    FILLROW(2); CPA_COMMIT();
    __syncwarp();

    float ssum = 0.f;

    // Uniform phases; base multiple of 11 so (base+q) % 11 == q.
    for (int base = 0; base < nrows; base += 11) {
#pragma unroll
        for (int q = 0; q < 11; ++q) {
            PHASE(q, base + q);
        }
    }

    // ---- deterministic block reduction ----
    __syncthreads();
#pragma unroll
    for (int off = 16; off; off >>= 1)
        ssum += __shfl_xor_sync(0xffffffffu, ssum, off);

    __shared__ float wsum[16];
    __shared__ bool  islast;
    if (l == 0) wsum[w] = ssum;
    __syncthreads();
    if (t == 0) {
        float v = 0.f;
#pragma unroll
        for (int i = 0; i < 16; ++i) v += wsum[i];
        g_partials[plane * NBANDS + band] = v;
        __threadfence();
        const unsigned n = atomicAdd(&g_count, 1u);
        islast = (n == (unsigned)(NBLOCKS - 1));
    }
    __syncthreads();

    // ---- last CTA: fixed-order (deterministic) final reduction ----
    if (islast) {
        __threadfence();
        float v = (t < NBLOCKS) ? g_partials[t] : 0.f;
#pragma unroll
        for (int off = 16; off; off >>= 1)
            v += __shfl_xor_sync(0xffffffffu, v, off);
        if (l == 0) wsum[w] = v;
        __syncthreads();
        if (t == 0) {
            float s = 0.f;
#pragma unroll
            for (int i = 0; i < 16; ++i) s += wsum[i];
            out[0] = s * (1.0f / 12582912.0f);  // / (16*3*512*512)
            g_count = 0u;                        // reset for next graph replay
        }
    }
}

extern "C" void kernel_launch(void* const* d_in, const int* in_sizes, int n_in,
                              void* d_out, int out_size)
{
    const float* img1 = (const float*)d_in[0];
    const float* img2 = (const float*)d_in[1];
    (void)in_sizes; (void)n_in; (void)out_size;

    dim3 grid(NBANDS, NPLANES);
    ssim_main<<<grid, NT>>>(img1, img2, (float*)d_out);
}

// round 8
// speedup vs baseline: 2.2220x; 1.0660x over previous
#include <cuda_runtime.h>

// ---------------------------------------------------------------------------
// SSIM (16,3,512,512) fp32, 11x11 Gaussian (sigma=1.5), zero pad, global mean.
// Separable conv; horizontal 11-tap from WARP-PRIVATE SMEM halo segments;
// vertical 11-tap via static mod-11 register ring (zero shifts).
// cp.async GMEM->SMEM pipeline depth 3 over 8 rotating buffers.
// NEW: Hadamard field reduction. S=x+y, D=x-y (in-place SMEM transform, once
// per pixel). Only 4 conv fields needed: conv(S), conv(D), conv(S^2),
// conv(D^2); all SSIM terms recovered from sums/differences:
//   m11+m22=(p^2+q^2)/2, 2*m12=(p^2-q^2)/2,
//   E[x^2]+E[y^2]=(SS+DD)/2, 2*E[xy]=(SS-DD)/2.
// Ring drops 55->44 FFMA, h-conv 70->62, -11 live registers.
// ---------------------------------------------------------------------------

#define IMW     512
#define IMH     512
#define NT      512                 // one thread per column
#define TH      171                 // output rows per band (3 bands cover 512)
#define NBANDS  3
#define NPLANES 48                  // 16 * 3
#define NBLOCKS (NPLANES * NBANDS)  // 144 CTAs -> single wave
#define SSIM_C1 0.0001f
#define SSIM_C2 0.0009f

__device__ float        g_partials[NBLOCKS];
__device__ unsigned int g_count;    // zero-init; reset by last block each run

#define CPA4(daddr, sptr) \
    asm volatile("cp.async.ca.shared.global [%0], [%1], 4;" \
                 :: "r"(daddr), "l"(sptr))
#define CPA_COMMIT() asm volatile("cp.async.commit_group;" ::: "memory")
#define CPA_WAIT2()  asm volatile("cp.async.wait_group 2;"  ::: "memory")

// One row-phase. P must be a compile-time constant == ir mod 11.
#define PHASE(P, IRV) do {                                                    \
    const int ir_ = (IRV);                                                    \
    if (ir_ < nrows) {                                                        \
        CPA_WAIT2();               /* row ir_ (issued 3 phases ago) done */   \
        {   /* in-place (x,y) -> (S,D) on OWN lanes' slots of row ir_ */      \
            float2* rb = seg[ir_ & 7][w];                                     \
            const float2 v = rb[l];                                           \
            rb[l] = make_float2(v.x + v.y, v.x - v.y);                        \
            if (tailst) {                                                     \
                const float2 u = rb[32 + l];                                  \
                rb[32 + l] = make_float2(u.x + u.y, u.x - u.y);               \
            }                                                                 \
        }                                                                     \
        FILLROW(ir_ + 3);          /* async fill into buf[(ir_+3)&7] */       \
        CPA_COMMIT();              /* unconditional: uniform group count */   \
        __syncwarp();                                                         \
        {                                                                     \
            const float2* sp = &seg[ir_ & 7][w][l];                           \
            float hp, hq, hss, hdd;                                           \
            {   /* center tap: (S,D) in (.x,.y) */                            \
                const float2 c = sp[5];                                       \
                hp  = W[5] * c.x;                                             \
                hq  = W[5] * c.y;                                             \
                hss = W[5] * (c.x * c.x);                                     \
                hdd = W[5] * (c.y * c.y);                                     \
            }                                                                 \
            _Pragma("unroll")                                                 \
            for (int k = 0; k < 5; ++k) {   /* symmetric pairs (k, 10-k) */   \
                const float2 a = sp[k];                                       \
                const float2 b = sp[10 - k];                                  \
                hp += W[k] * (a.x + b.x);                                     \
                hq += W[k] * (a.y + b.y);                                     \
                const float ss = a.x * a.x + b.x * b.x;                       \
                const float dd = a.y * a.y + b.y * b.y;                       \
                hss += W[k] * ss;                                             \
                hdd += W[k] * dd;                                             \
            }                                                                 \
            _Pragma("unroll")                                                 \
            for (int s = 0; s < 11; ++s) {                                    \
                const int d = ((P) - s + 11) % 11;  /* compile-time */        \
                const float wd = W[d];                                        \
                AP[s] += wd * hp;  AQ[s] += wd * hq;                          \
                AS[s] += wd * hss; AD[s] += wd * hdd;                         \
            }                                                                 \
            const int e_ = ((P) + 1) % 11;          /* compile-time */        \
            if (ir_ >= 10) {        /* output row m = ir-10 is real */        \
                const float p  = AP[e_], q  = AQ[e_];                         \
                const float sv = AS[e_], dv = AD[e_];                         \
                const float a2 = p * p;                                       \
                const float b2 = q * q;                                       \
                const float U  = a2 + b2;       /* = 2(m11+m22) */            \
                const float V  = a2 - b2;       /* = 4*m12      */            \
                const float M  = sv + dv;       /* = 2(Ex2+Ey2) */            \
                const float N2 = sv - dv;       /* = 4*Exy      */            \
                /* num = (2m12+C1)(2s12+C2); 2m12=V/2, 2s12=(N2-V)/2 */       \
                const float t1  = 0.5f * V + SSIM_C1;                         \
                const float t2  = 0.5f * (N2 - V) + SSIM_C2;                  \
                /* den = (m11+m22+C1)(s1+s2+C2); m11+m22=U/2 */               \
                const float t3  = 0.5f * U + SSIM_C1;                         \
                const float t4  = 0.5f * (M - U) + SSIM_C2;                   \
                ssum += __fdividef(t1 * t2, t3 * t4);                         \
            }                                                                 \
            AP[e_] = 0.f; AQ[e_] = 0.f; AS[e_] = 0.f; AD[e_] = 0.f;           \
        }                                                                     \
    }                                                                         \
} while (0)

__global__ void __launch_bounds__(NT, 1)
ssim_main(const float* __restrict__ img1, const float* __restrict__ img2,
          float* __restrict__ out)
{
    // Normalized 1D Gaussian, sigma=1.5, 11 taps (compile-time immediates)
    const float W[11] = {
        0.00102838f, 0.00759874f, 0.03600077f, 0.10936069f, 0.21300553f,
        0.26601180f,
        0.21300553f, 0.10936069f, 0.03600077f, 0.00759874f, 0.00102838f
    };

    const int band  = blockIdx.x;           // 0..2
    const int plane = blockIdx.y;           // 0..47
    const int t     = threadIdx.x;          // column 0..511
    const int l     = t & 31;               // lane
    const int w     = t >> 5;               // warp
    const int r0    = band * TH;
    const int rows  = (IMH - r0 < TH) ? (IMH - r0) : TH;   // 171/171/170
    const int nrows = rows + 10;
    const int pbase = plane * (IMW * IMH);

    // Warp-private 8-deep rotating halo segments.
    // Filled as (img1, img2) by cp.async; transformed in place to (S, D).
    // seg[buf][w][j], j in [0,42): pixel pair at image column 32*w - 5 + j.
    __shared__ float2 seg[8][16][44];

    // Static ring: slot s holds partials for output rows m with m % 11 == s.
    float AP[11], AQ[11], AS[11], AD[11];
#pragma unroll
    for (int j = 0; j < 11; ++j) {
        AP[j] = 0.f; AQ[j] = 0.f; AS[j] = 0.f; AD[j] = 0.f;
    }

    // Column mapping (identical for every row):
    //   slot j = l      <-> col t - 5   (valid iff t >= 5)
    //   slot j = 32 + l <-> col t + 27  (exists iff l < 10, valid iff < 512)
    const int  c1     = t - 5;
    const bool mainok = (t >= 5);
    const int  c2     = t + 27;
    const bool tailst = (l < 10);
    const bool tailok = tailst && (c2 < IMW);

    // u32 shared address of this warp+lane's slot in buffer 0
    unsigned sbu;
    asm("{ .reg .u64 tt; cvta.to.shared.u64 tt, %1; cvt.u32.u64 %0, tt; }"
        : "=r"(sbu) : "l"(&seg[0][w][l]));
    const unsigned BSTRIDE = 16u * 44u * 8u;   // bytes per buffer (5632)
    const unsigned TAILOFF = 32u * 8u;         // slot (32+l) - slot l (256 B)

    auto FILLROW = [&](int rn) {
        if (rn < nrows) {
            const int gr = r0 - 5 + rn;         // global row (zero pad if OOB)
            const int b  = rn & 7;
            const unsigned d = sbu + (unsigned)b * BSTRIDE;
            if ((unsigned)gr < (unsigned)IMH) {
                const float* p1 = img1 + pbase + gr * IMW;
                const float* p2 = img2 + pbase + gr * IMW;
                if (mainok) { CPA4(d, p1 + c1);               // x
                              CPA4(d + 4u, p2 + c1); }        // y
                if (tailok) { CPA4(d + TAILOFF, p1 + c2);
                              CPA4(d + TAILOFF + 4u, p2 + c2); }
            } else {
                if (mainok) seg[b][w][l]      = make_float2(0.f, 0.f);
                if (tailst) seg[b][w][32 + l] = make_float2(0.f, 0.f);
            }
        }
    };

    // Pre-zero slots never written by cp.async (col-invalid); all 8 buffers.
#pragma unroll
    for (int b = 0; b < 8; ++b) {
        if (!mainok)           seg[b][w][l]      = make_float2(0.f, 0.f);
        if (tailst && !tailok) seg[b][w][32 + l] = make_float2(0.f, 0.f);
    }

    // Prologue: rows 0,1,2 in flight as three groups.
    FILLROW(0); CPA_COMMIT();
    FILLROW(1); CPA_COMMIT();
    FILLROW(2); CPA_COMMIT();
    __syncwarp();

    float ssum = 0.f;

    // Uniform phases; base multiple of 11 so (base+q) % 11 == q.
    for (int base = 0; base < nrows; base += 11) {
#pragma unroll
        for (int q = 0; q < 11; ++q) {
            PHASE(q, base + q);
        }
    }

    // ---- deterministic block reduction ----
    __syncthreads();
#pragma unroll
    for (int off = 16; off; off >>= 1)
        ssum += __shfl_xor_sync(0xffffffffu, ssum, off);

    __shared__ float wsum[16];
    __shared__ bool  islast;
    if (l == 0) wsum[w] = ssum;
    __syncthreads();
    if (t == 0) {
        float v = 0.f;
#pragma unroll
        for (int i = 0; i < 16; ++i) v += wsum[i];
        g_partials[plane * NBANDS + band] = v;
        __threadfence();
        const unsigned n = atomicAdd(&g_count, 1u);
        islast = (n == (unsigned)(NBLOCKS - 1));
    }
    __syncthreads();

    // ---- last CTA: fixed-order (deterministic) final reduction ----
    if (islast) {
        __threadfence();
        float v = (t < NBLOCKS) ? g_partials[t] : 0.f;
#pragma unroll
        for (int off = 16; off; off >>= 1)
            v += __shfl_xor_sync(0xffffffffu, v, off);
        if (l == 0) wsum[w] = v;
        __syncthreads();
        if (t == 0) {
            float s = 0.f;
#pragma unroll
            for (int i = 0; i < 16; ++i) s += wsum[i];
            out[0] = s * (1.0f / 12582912.0f);  // / (16*3*512*512)
            g_count = 0u;                        // reset for next graph replay
        }
    }
}

extern "C" void kernel_launch(void* const* d_in, const int* in_sizes, int n_in,
                              void* d_out, int out_size)
{
    const float* img1 = (const float*)d_in[0];
    const float* img2 = (const float*)d_in[1];
    (void)in_sizes; (void)n_in; (void)out_size;

    dim3 grid(NBANDS, NPLANES);
    ssim_main<<<grid, NT>>>(img1, img2, (float*)d_out);
}

// round 9
// speedup vs baseline: 2.3287x; 1.0480x over previous
#include <cuda_runtime.h>

// ---------------------------------------------------------------------------
// SSIM (16,3,512,512) fp32, 11x11 Gaussian (sigma=1.5), zero pad, global mean.
// Separable conv; horizontal 11-tap from WARP-PRIVATE SMEM halo segments;
// vertical 11-tap via static mod-11 register ring (zero shifts).
// cp.async GMEM->SMEM pipeline depth 3 over 8 rotating buffers.
// Hadamard fields: S=x+y, D=x-y (in-place SMEM transform once per pixel).
// NEW: full f32x2 datapath. (S,D) pairs are loaded as ld.shared.b64 (no
// packing movs), h-conv and vertical ring run 2-wide (fma.rn.f32x2 /
// mul.rn.f32x2 / add.rn.f32x2); single unpack per output row.
// ---------------------------------------------------------------------------

#define IMW     512
#define IMH     512
#define NT      512                 // one thread per column
#define TH      171                 // output rows per band (3 bands cover 512)
#define NBANDS  3
#define NPLANES 48                  // 16 * 3
#define NBLOCKS (NPLANES * NBANDS)  // 144 CTAs -> single wave
#define SSIM_C1 0.0001f
#define SSIM_C2 0.0009f

typedef unsigned long long ull;

__device__ float        g_partials[NBLOCKS];
__device__ unsigned int g_count;    // zero-init; reset by last block each run

#define CPA4(daddr, sptr) \
    asm volatile("cp.async.ca.shared.global [%0], [%1], 4;" \
                 :: "r"(daddr), "l"(sptr))
#define CPA_COMMIT() asm volatile("cp.async.commit_group;" ::: "memory")
#define CPA_WAIT2()  asm volatile("cp.async.wait_group 2;"  ::: "memory")

#define LDS64(d, a) \
    asm volatile("ld.shared.b64 %0, [%1];" : "=l"(d) : "r"(a))
#define ADD2(d, a, b) \
    asm("add.rn.f32x2 %0, %1, %2;" : "=l"(d) : "l"(a), "l"(b))
#define MUL2(d, a, b) \
    asm("mul.rn.f32x2 %0, %1, %2;" : "=l"(d) : "l"(a), "l"(b))
#define FMA2(d, a, b, c) \
    asm("fma.rn.f32x2 %0, %1, %2, %3;" : "=l"(d) : "l"(a), "l"(b), "l"(c))
#define UNPACK2(lo, hi, s) \
    asm("mov.b64 {%0, %1}, %2;" : "=f"(lo), "=f"(hi) : "l"(s))

// One row-phase. P must be a compile-time constant == ir mod 11.
#define PHASE(P, IRV) do {                                                    \
    const int ir_ = (IRV);                                                    \
    if (ir_ < nrows) {                                                        \
        CPA_WAIT2();               /* row ir_ (issued 3 phases ago) done */   \
        {   /* in-place (x,y) -> (S,D) on OWN lanes' slots of row ir_ */      \
            float2* rb = seg[ir_ & 7][w];                                     \
            const float2 v = rb[l];                                           \
            rb[l] = make_float2(v.x + v.y, v.x - v.y);                        \
            if (tailst) {                                                     \
                const float2 u = rb[32 + l];                                  \
                rb[32 + l] = make_float2(u.x + u.y, u.x - u.y);               \
            }                                                                 \
        }                                                                     \
        FILLROW(ir_ + 3);          /* async fill into buf[(ir_+3)&7] */       \
        CPA_COMMIT();              /* unconditional: uniform group count */   \
        __syncwarp();                                                         \
        {                                                                     \
            const unsigned rb_ = sbu + (unsigned)(ir_ & 7) * BSTRIDE;         \
            ull v[11];                                                        \
            _Pragma("unroll")                                                 \
            for (int k = 0; k < 11; ++k) LDS64(v[k], rb_ + 8u * k);           \
            ull hpq, hsd, tc;            /* (hp|hq), (hss|hdd) */             \
            MUL2(hpq, v[5], W2[5]);                                           \
            MUL2(tc,  v[5], v[5]);                                            \
            MUL2(hsd, tc, W2[5]);                                             \
            _Pragma("unroll")                                                 \
            for (int k = 0; k < 5; ++k) {   /* symmetric pairs (k, 10-k) */   \
                ull ab, sq;                                                   \
                ADD2(ab, v[k], v[10 - k]);                                    \
                FMA2(hpq, ab, W2[k], hpq);                                    \
                MUL2(sq, v[k], v[k]);                                         \
                FMA2(sq, v[10 - k], v[10 - k], sq);                           \
                FMA2(hsd, sq, W2[k], hsd);                                    \
            }                                                                 \
            _Pragma("unroll")                                                 \
            for (int s = 0; s < 11; ++s) {                                    \
                const int d = ((P) - s + 11) % 11;  /* compile-time */        \
                FMA2(APQ[s], hpq, W2[d], APQ[s]);                             \
                FMA2(ASD[s], hsd, W2[d], ASD[s]);                             \
            }                                                                 \
            const int e_ = ((P) + 1) % 11;          /* compile-time */        \
            if (ir_ >= 10) {        /* output row m = ir-10 is real */        \
                float p, q, sv, dv;                                           \
                UNPACK2(p, q, APQ[e_]);                                       \
                UNPACK2(sv, dv, ASD[e_]);                                     \
                const float a2 = p * p;                                       \
                const float b2 = q * q;                                       \
                const float U  = a2 + b2;                                     \
                const float V  = a2 - b2;                                     \
                const float M  = sv + dv;                                     \
                const float N2 = sv - dv;                                     \
                const float t1 = 0.5f * V + SSIM_C1;                          \
                const float t2 = 0.5f * (N2 - V) + SSIM_C2;                   \
                const float t3 = 0.5f * U + SSIM_C1;                          \
                const float t4 = 0.5f * (M - U) + SSIM_C2;                    \
                ssum += __fdividef(t1 * t2, t3 * t4);                         \
            }                                                                 \
            APQ[e_] = 0ULL; ASD[e_] = 0ULL;                                   \
        }                                                                     \
    }                                                                         \
} while (0)

__global__ void __launch_bounds__(NT, 1)
ssim_main(const float* __restrict__ img1, const float* __restrict__ img2,
          float* __restrict__ out)
{
    // Normalized 1D Gaussian, sigma=1.5, 11 taps (compile-time immediates)
    const float W[11] = {
        0.00102838f, 0.00759874f, 0.03600077f, 0.10936069f, 0.21300553f,
        0.26601180f,
        0.21300553f, 0.10936069f, 0.03600077f, 0.00759874f, 0.00102838f
    };
    // Duplicated 64-bit weight pairs (w|w) for f32x2 ops (constant-folded)
    ull W2[11];
#pragma unroll
    for (int k = 0; k < 11; ++k) {
        const unsigned u = __float_as_uint(W[k]);
        W2[k] = ((ull)u << 32) | (ull)u;
    }

    const int band  = blockIdx.x;           // 0..2
    const int plane = blockIdx.y;           // 0..47
    const int t     = threadIdx.x;          // column 0..511
    const int l     = t & 31;               // lane
    const int w     = t >> 5;               // warp
    const int r0    = band * TH;
    const int rows  = (IMH - r0 < TH) ? (IMH - r0) : TH;   // 171/171/170
    const int nrows = rows + 10;
    const int pbase = plane * (IMW * IMH);

    // Warp-private 8-deep rotating halo segments.
    // Filled as (img1, img2) by cp.async; transformed in place to (S, D).
    // seg[buf][w][j], j in [0,42): pixel pair at image column 32*w - 5 + j.
    __shared__ float2 seg[8][16][44];

    // Static ring (packed): slot s holds (P|Q) and (SS|DD) partials for
    // output rows m with m % 11 == s.
    ull APQ[11], ASD[11];
#pragma unroll
    for (int j = 0; j < 11; ++j) { APQ[j] = 0ULL; ASD[j] = 0ULL; }

    // Column mapping (identical for every row):
    //   slot j = l      <-> col t - 5   (valid iff t >= 5)
    //   slot j = 32 + l <-> col t + 27  (exists iff l < 10, valid iff < 512)
    const int  c1     = t - 5;
    const bool mainok = (t >= 5);
    const int  c2     = t + 27;
    const bool tailst = (l < 10);
    const bool tailok = tailst && (c2 < IMW);

    // u32 shared address of this warp+lane's slot in buffer 0
    unsigned sbu;
    asm("{ .reg .u64 tt; cvta.to.shared.u64 tt, %1; cvt.u32.u64 %0, tt; }"
        : "=r"(sbu) : "l"(&seg[0][w][l]));
    const unsigned BSTRIDE = 16u * 44u * 8u;   // bytes per buffer (5632)
    const unsigned TAILOFF = 32u * 8u;         // slot (32+l) - slot l (256 B)

    auto FILLROW = [&](int rn) {
        if (rn < nrows) {
            const int gr = r0 - 5 + rn;         // global row (zero pad if OOB)
            const int b  = rn & 7;
            const unsigned d = sbu + (unsigned)b * BSTRIDE;
            if ((unsigned)gr < (unsigned)IMH) {
                const float* p1 = img1 + pbase + gr * IMW;
                const float* p2 = img2 + pbase + gr * IMW;
                if (mainok) { CPA4(d, p1 + c1);               // x
                              CPA4(d + 4u, p2 + c1); }        // y
                if (tailok) { CPA4(d + TAILOFF, p1 + c2);
                              CPA4(d + TAILOFF + 4u, p2 + c2); }
            } else {
                if (mainok) seg[b][w][l]      = make_float2(0.f, 0.f);
                if (tailst) seg[b][w][32 + l] = make_float2(0.f, 0.f);
            }
        }
    };

    // Pre-zero slots never written by cp.async (col-invalid); all 8 buffers.
#pragma unroll
    for (int b = 0; b < 8; ++b) {
        if (!mainok)           seg[b][w][l]      = make_float2(0.f, 0.f);
        if (tailst && !tailok) seg[b][w][32 + l] = make_float2(0.f, 0.f);
    }

    // Prologue: rows 0,1,2 in flight as three groups.
    FILLROW(0); CPA_COMMIT();
    FILLROW(1); CPA_COMMIT();
    FILLROW(2); CPA_COMMIT();
    __syncwarp();

    float ssum = 0.f;

    // Uniform phases; base multiple of 11 so (base+q) % 11 == q.
    for (int base = 0; base < nrows; base += 11) {
#pragma unroll
        for (int q = 0; q < 11; ++q) {
            PHASE(q, base + q);
        }
    }

    // ---- deterministic block reduction ----
    __syncthreads();
#pragma unroll
    for (int off = 16; off; off >>= 1)
        ssum += __shfl_xor_sync(0xffffffffu, ssum, off);

    __shared__ float wsum[16];
    __shared__ bool  islast;
    if (l == 0) wsum[w] = ssum;
    __syncthreads();
    if (t == 0) {
        float v = 0.f;
#pragma unroll
        for (int i = 0; i < 16; ++i) v += wsum[i];
        g_partials[plane * NBANDS + band] = v;
        __threadfence();
        const unsigned n = atomicAdd(&g_count, 1u);
        islast = (n == (unsigned)(NBLOCKS - 1));
    }
    __syncthreads();

    // ---- last CTA: fixed-order (deterministic) final reduction ----
    if (islast) {
        __threadfence();
        float v = (t < NBLOCKS) ? g_partials[t] : 0.f;
#pragma unroll
        for (int off = 16; off; off >>= 1)
            v += __shfl_xor_sync(0xffffffffu, v, off);
        if (l == 0) wsum[w] = v;
        __syncthreads();
        if (t == 0) {
            float s = 0.f;
#pragma unroll
            for (int i = 0; i < 16; ++i) s += wsum[i];
            out[0] = s * (1.0f / 12582912.0f);  // / (16*3*512*512)
            g_count = 0u;                        // reset for next graph replay
        }
    }
}

extern "C" void kernel_launch(void* const* d_in, const int* in_sizes, int n_in,
                              void* d_out, int out_size)
{
    const float* img1 = (const float*)d_in[0];
    const float* img2 = (const float*)d_in[1];
    (void)in_sizes; (void)n_in; (void)out_size;

    dim3 grid(NBANDS, NPLANES);
    ssim_main<<<grid, NT>>>(img1, img2, (float*)d_out);
}

// round 10
// speedup vs baseline: 2.3392x; 1.0045x over previous
#include <cuda_runtime.h>

// ---------------------------------------------------------------------------
// SSIM (16,3,512,512) fp32, 11x11 Gaussian (sigma=1.5), zero pad, global mean.
// Separable conv; horizontal 11-tap from WARP-PRIVATE SMEM halo segments;
// vertical 11-tap via static mod-11 register ring (zero shifts).
// cp.async GMEM->SMEM pipeline depth 3 over 8 rotating buffers.
// Hadamard fields: S=x+y, D=x-y (in-place SMEM transform once per pixel).
// f32x2 datapath: (S,D) loaded as ld.shared.b64, h-conv + ring 2-wide.
// NEW: all f32x2 accumulations use "+l" read-write constraints
// (fma.rn.f32x2 %0,%1,%2,%0) so ptxas allocates acc==addend pair and emits
// zero MOV64 copies (R9 lost ~44 ALU slots/row to them).
// ---------------------------------------------------------------------------

#define IMW     512
#define IMH     512
#define NT      512                 // one thread per column
#define TH      171                 // output rows per band (3 bands cover 512)
#define NBANDS  3
#define NPLANES 48                  // 16 * 3
#define NBLOCKS (NPLANES * NBANDS)  // 144 CTAs -> single wave
#define SSIM_C1 0.0001f
#define SSIM_C2 0.0009f

typedef unsigned long long ull;

__device__ float        g_partials[NBLOCKS];
__device__ unsigned int g_count;    // zero-init; reset by last block each run

#define CPA4(daddr, sptr) \
    asm volatile("cp.async.ca.shared.global [%0], [%1], 4;" \
                 :: "r"(daddr), "l"(sptr))
#define CPA_COMMIT() asm volatile("cp.async.commit_group;" ::: "memory")
#define CPA_WAIT2()  asm volatile("cp.async.wait_group 2;"  ::: "memory")

#define LDS64(d, a) \
    asm volatile("ld.shared.b64 %0, [%1];" : "=l"(d) : "r"(a))
#define ADD2(d, a, b) \
    asm("add.rn.f32x2 %0, %1, %2;" : "=l"(d) : "l"(a), "l"(b))
#define MUL2(d, a, b) \
    asm("mul.rn.f32x2 %0, %1, %2;" : "=l"(d) : "l"(a), "l"(b))
// In-place accumulate: output pair tied to addend pair -> no MOV64 copies.
#define FMA2ACC(acc, a, b) \
    asm("fma.rn.f32x2 %0, %1, %2, %0;" : "+l"(acc) : "l"(a), "l"(b))
#define UNPACK2(lo, hi, s) \
    asm("mov.b64 {%0, %1}, %2;" : "=f"(lo), "=f"(hi) : "l"(s))

// One row-phase. P must be a compile-time constant == ir mod 11.
#define PHASE(P, IRV) do {                                                    \
    const int ir_ = (IRV);                                                    \
    if (ir_ < nrows) {                                                        \
        CPA_WAIT2();               /* row ir_ (issued 3 phases ago) done */   \
        {   /* in-place (x,y) -> (S,D) on OWN lanes' slots of row ir_ */      \
            float2* rb = seg[ir_ & 7][w];                                     \
            const float2 v = rb[l];                                           \
            rb[l] = make_float2(v.x + v.y, v.x - v.y);                        \
            if (tailst) {                                                     \
                const float2 u = rb[32 + l];                                  \
                rb[32 + l] = make_float2(u.x + u.y, u.x - u.y);               \
            }                                                                 \
        }                                                                     \
        FILLROW(ir_ + 3);          /* async fill into buf[(ir_+3)&7] */       \
        CPA_COMMIT();              /* unconditional: uniform group count */   \
        __syncwarp();                                                         \
        {                                                                     \
            const unsigned rb_ = sbu + (unsigned)(ir_ & 7) * BSTRIDE;         \
            ull v[11];                                                        \
            _Pragma("unroll")                                                 \
            for (int k = 0; k < 11; ++k) LDS64(v[k], rb_ + 8u * k);           \
            ull hpq, hsd, tc;            /* (hp|hq), (hss|hdd) */             \
            MUL2(hpq, v[5], W2[5]);                                           \
            MUL2(tc,  v[5], v[5]);                                            \
            MUL2(hsd, tc, W2[5]);                                             \
            _Pragma("unroll")                                                 \
            for (int k = 0; k < 5; ++k) {   /* symmetric pairs (k, 10-k) */   \
                ull ab, sq;                                                   \
                ADD2(ab, v[k], v[10 - k]);                                    \
                FMA2ACC(hpq, ab, W2[k]);                                      \
                MUL2(sq, v[k], v[k]);                                         \
                FMA2ACC(sq, v[10 - k], v[10 - k]);  /* wait: wrong form */    \
                FMA2ACC(hsd, sq, W2[k]);                                      \
            }                                                                 \
            _Pragma("unroll")                                                 \
            for (int s = 0; s < 11; ++s) {                                    \
                const int d = ((P) - s + 11) % 11;  /* compile-time */        \
                FMA2ACC(APQ[s], hpq, W2[d]);                                  \
                FMA2ACC(ASD[s], hsd, W2[d]);                                  \
            }                                                                 \
            const int e_ = ((P) + 1) % 11;          /* compile-time */        \
            if (ir_ >= 10) {        /* output row m = ir-10 is real */        \
                float p, q, sv, dv;                                           \
                UNPACK2(p, q, APQ[e_]);                                       \
                UNPACK2(sv, dv, ASD[e_]);                                     \
                const float a2 = p * p;                                       \
                const float b2 = q * q;                                       \
                const float U  = a2 + b2;                                     \
                const float V  = a2 - b2;                                     \
                const float M  = sv + dv;                                     \
                const float N2 = sv - dv;                                     \
                const float t1 = 0.5f * V + SSIM_C1;                          \
                const float t2 = 0.5f * (N2 - V) + SSIM_C2;                   \
                const float t3 = 0.5f * U + SSIM_C1;                          \
                const float t4 = 0.5f * (M - U) + SSIM_C2;                    \
                ssum += __fdividef(t1 * t2, t3 * t4);                         \
            }                                                                 \
            APQ[e_] = 0ULL; ASD[e_] = 0ULL;                                   \
        }                                                                     \
    }                                                                         \
} while (0)

__global__ void __launch_bounds__(NT, 1)
ssim_main(const float* __restrict__ img1, const float* __restrict__ img2,
          float* __restrict__ out)
{
    // Normalized 1D Gaussian, sigma=1.5, 11 taps (compile-time immediates)
    const float W[11] = {
        0.00102838f, 0.00759874f, 0.03600077f, 0.10936069f, 0.21300553f,
        0.26601180f,
        0.21300553f, 0.10936069f, 0.03600077f, 0.00759874f, 0.00102838f
    };
    // Duplicated 64-bit weight pairs (w|w) for f32x2 ops (constant-folded)
    ull W2[11];
#pragma unroll
    for (int k = 0; k < 11; ++k) {
        const unsigned u = __float_as_uint(W[k]);
        W2[k] = ((ull)u << 32) | (ull)u;
    }

    const int band  = blockIdx.x;           // 0..2
    const int plane = blockIdx.y;           // 0..47
    const int t     = threadIdx.x;          // column 0..511
    const int l     = t & 31;               // lane
    const int w     = t >> 5;               // warp
    const int r0    = band * TH;
    const int rows  = (IMH - r0 < TH) ? (IMH - r0) : TH;   // 171/171/170
    const int nrows = rows + 10;
    const int pbase = plane * (IMW * IMH);

    // Warp-private 8-deep rotating halo segments.
    // Filled as (img1, img2) by cp.async; transformed in place to (S, D).
    // seg[buf][w][j], j in [0,42): pixel pair at image column 32*w - 5 + j.
    __shared__ float2 seg[8][16][44];

    // Static ring (packed): slot s holds (P|Q) and (SS|DD) partials for
    // output rows m with m % 11 == s.
    ull APQ[11], ASD[11];
#pragma unroll
    for (int j = 0; j < 11; ++j) { APQ[j] = 0ULL; ASD[j] = 0ULL; }

    // Column mapping (identical for every row):
    //   slot j = l      <-> col t - 5   (valid iff t >= 5)
    //   slot j = 32 + l <-> col t + 27  (exists iff l < 10, valid iff < 512)
    const int  c1     = t - 5;
    const bool mainok = (t >= 5);
    const int  c2     = t + 27;
    const bool tailst = (l < 10);
    const bool tailok = tailst && (c2 < IMW);

    // u32 shared address of this warp+lane's slot in buffer 0
    unsigned sbu;
    asm("{ .reg .u64 tt; cvta.to.shared.u64 tt, %1; cvt.u32.u64 %0, tt; }"
        : "=r"(sbu) : "l"(&seg[0][w][l]));
    const unsigned BSTRIDE = 16u * 44u * 8u;   // bytes per buffer (5632)
    const unsigned TAILOFF = 32u * 8u;         // slot (32+l) - slot l (256 B)

    auto FILLROW = [&](int rn) {
        if (rn < nrows) {
            const int gr = r0 - 5 + rn;         // global row (zero pad if OOB)
            const int b  = rn & 7;
            const unsigned d = sbu + (unsigned)b * BSTRIDE;
            if ((unsigned)gr < (unsigned)IMH) {
                const float* p1 = img1 + pbase + gr * IMW;
                const float* p2 = img2 + pbase + gr * IMW;
                if (mainok) { CPA4(d, p1 + c1);               // x
                              CPA4(d + 4u, p2 + c1); }        // y
                if (tailok) { CPA4(d + TAILOFF, p1 + c2);
                              CPA4(d + TAILOFF + 4u, p2 + c2); }
            } else {
                if (mainok) seg[b][w][l]      = make_float2(0.f, 0.f);
                if (tailst) seg[b][w][32 + l] = make_float2(0.f, 0.f);
            }
        }
    };

    // Pre-zero slots never written by cp.async (col-invalid); all 8 buffers.
#pragma unroll
    for (int b = 0; b < 8; ++b) {
        if (!mainok)           seg[b][w][l]      = make_float2(0.f, 0.f);
        if (tailst && !tailok) seg[b][w][32 + l] = make_float2(0.f, 0.f);
    }

    // Prologue: rows 0,1,2 in flight as three groups.
    FILLROW(0); CPA_COMMIT();
    FILLROW(1); CPA_COMMIT();
    FILLROW(2); CPA_COMMIT();
    __syncwarp();

    float ssum = 0.f;

    // Uniform phases; base multiple of 11 so (base+q) % 11 == q.
    for (int base = 0; base < nrows; base += 11) {
#pragma unroll
        for (int q = 0; q < 11; ++q) {
            PHASE(q, base + q);
        }
    }

    // ---- deterministic block reduction ----
    __syncthreads();
#pragma unroll
    for (int off = 16; off; off >>= 1)
        ssum += __shfl_xor_sync(0xffffffffu, ssum, off);

    __shared__ float wsum[16];
    __shared__ bool  islast;
    if (l == 0) wsum[w] = ssum;
    __syncthreads();
    if (t == 0) {
        float v = 0.f;
#pragma unroll
        for (int i = 0; i < 16; ++i) v += wsum[i];
        g_partials[plane * NBANDS + band] = v;
        __threadfence();
        const unsigned n = atomicAdd(&g_count, 1u);
        islast = (n == (unsigned)(NBLOCKS - 1));
    }
    __syncthreads();

    // ---- last CTA: fixed-order (deterministic) final reduction ----
    if (islast) {
        __threadfence();
        float v = (t < NBLOCKS) ? g_partials[t] : 0.f;
#pragma unroll
        for (int off = 16; off; off >>= 1)
            v += __shfl_xor_sync(0xffffffffu, v, off);
        if (l == 0) wsum[w] = v;
        __syncthreads();
        if (t == 0) {
            float s = 0.f;
#pragma unroll
            for (int i = 0; i < 16; ++i) s += wsum[i];
            out[0] = s * (1.0f / 12582912.0f);  // / (16*3*512*512)
            g_count = 0u;                        // reset for next graph replay
        }
    }
}

extern "C" void kernel_launch(void* const* d_in, const int* in_sizes, int n_in,
                              void* d_out, int out_size)
{
    const float* img1 = (const float*)d_in[0];
    const float* img2 = (const float*)d_in[1];
    (void)in_sizes; (void)n_in; (void)out_size;

    dim3 grid(NBANDS, NPLANES);
    ssim_main<<<grid, NT>>>(img1, img2, (float*)d_out);
}

// round 11
// speedup vs baseline: 2.6113x; 1.1163x over previous
#include <cuda_runtime.h>

// ---------------------------------------------------------------------------
// SSIM (16,3,512,512) fp32, 11x11 Gaussian (sigma=1.5), zero pad, global mean.
// Separable conv; warp-private SMEM halo segments; static mod-11 f32x2 ring.
// cp.async depth-3 pipeline over 8 rotating buffers. Hadamard fields (S,D).
// R11: bookkeeping strip — ring reset folded into a MUL2 overwrite at tap
// d==0, guard-free main blocks + guarded tail, IMAD.WIDE fill addressing
// with PTX immediate offsets, transform addressed off the h-conv base.
// ---------------------------------------------------------------------------

#define IMW     512
#define IMH     512
#define NT      512                 // one thread per column
#define TH      171                 // output rows per band (3 bands cover 512)
#define NBANDS  3
#define NPLANES 48                  // 16 * 3
#define NBLOCKS (NPLANES * NBANDS)  // 144 CTAs -> single wave
#define SSIM_C1 0.0001f
#define SSIM_C2 0.0009f

typedef unsigned long long ull;

__device__ float        g_partials[NBLOCKS];
__device__ unsigned int g_count;    // zero-init; reset by last block each run

#define CPA4(daddr, sptr) \
    asm volatile("cp.async.ca.shared.global [%0], [%1], 4;" \
                 :: "r"(daddr), "l"(sptr))
// tail column: dst slot +256 B (32 slots * 8B), src +128 B (32 floats)
#define CPA4T(daddr, sptr) \
    asm volatile("cp.async.ca.shared.global [%0+256], [%1+128], 4;" \
                 :: "r"(daddr), "l"(sptr))
#define CPA_COMMIT() asm volatile("cp.async.commit_group;" ::: "memory")
#define CPA_WAIT2()  asm volatile("cp.async.wait_group 2;"  ::: "memory")

#define LDS64(d, a) \
    asm volatile("ld.shared.b64 %0, [%1];" : "=l"(d) : "r"(a))
#define ADD2(d, a, b) \
    asm("add.rn.f32x2 %0, %1, %2;" : "=l"(d) : "l"(a), "l"(b))
#define MUL2(d, a, b) \
    asm("mul.rn.f32x2 %0, %1, %2;" : "=l"(d) : "l"(a), "l"(b))
#define FMA2ACC(acc, a, b) \
    asm("fma.rn.f32x2 %0, %1, %2, %0;" : "+l"(acc) : "l"(a), "l"(b))
#define UNPACK2(lo, hi, s) \
    asm("mov.b64 {%0, %1}, %2;" : "=f"(lo), "=f"(hi) : "l"(s))

// (x,y) -> (x+y, x-y) in place at shared address A (one 8-byte slot)
#define TRANS(A) do {                                                         \
    float xa_, xb_;                                                           \
    asm volatile("ld.shared.v2.f32 {%0,%1}, [%2];"                            \
                 : "=f"(xa_), "=f"(xb_) : "r"(A));                            \
    const float s_ = xa_ + xb_, d_ = xa_ - xb_;                               \
    asm volatile("st.shared.v2.f32 [%0], {%1,%2};"                            \
                 :: "r"(A), "f"(s_), "f"(d_));                                \
} while (0)

// h-conv + ring + extraction for row ir_ at buffer base rb_.
// P must be a compile-time constant == ir_ mod 11.
#define ROWCOMP(P, ir_, rb_) do {                                             \
    ull v[11];                                                                \
    _Pragma("unroll")                                                         \
    for (int k = 0; k < 11; ++k) LDS64(v[k], (rb_) + 8u * k);                 \
    ull hpq, hsd, tc;                                                         \
    MUL2(hpq, v[5], W2[5]);                                                   \
    MUL2(tc,  v[5], v[5]);                                                    \
    MUL2(hsd, tc, W2[5]);                                                     \
    _Pragma("unroll")                                                         \
    for (int k = 0; k < 5; ++k) {                                             \
        ull ab, sq;                                                           \
        ADD2(ab, v[k], v[10 - k]);                                            \
        FMA2ACC(hpq, ab, W2[k]);                                              \
        MUL2(sq, v[k], v[k]);                                                 \
        FMA2ACC(sq, v[10 - k], v[10 - k]);                                    \
        FMA2ACC(hsd, sq, W2[k]);                                              \
    }                                                                         \
    _Pragma("unroll")                                                         \
    for (int s = 0; s < 11; ++s) {                                            \
        const int d = ((P) - s + 11) % 11;      /* compile-time */            \
        if (s == (P)) {     /* tap d==0: new output starts -> overwrite */    \
            MUL2(APQ[s], hpq, W2[0]);                                         \
            MUL2(ASD[s], hsd, W2[0]);                                         \
        } else {                                                              \
            FMA2ACC(APQ[s], hpq, W2[d]);                                      \
            FMA2ACC(ASD[s], hsd, W2[d]);                                      \
        }                                                                     \
    }                                                                         \
    const int e_ = ((P) + 1) % 11;              /* compile-time */            \
    if ((ir_) >= 10) {          /* output row m = ir-10 is real */            \
        float p, q, sv, dv;                                                   \
        UNPACK2(p, q, APQ[e_]);                                               \
        UNPACK2(sv, dv, ASD[e_]);                                             \
        const float a2 = p * p;                                               \
        const float b2 = q * q;                                               \
        const float U  = a2 + b2;                                             \
        const float V  = a2 - b2;                                             \
        const float M  = sv + dv;                                             \
        const float N2 = sv - dv;                                             \
        const float t1 = 0.5f * V + SSIM_C1;                                  \
        const float t2 = 0.5f * (N2 - V) + SSIM_C2;                           \
        const float t3 = 0.5f * U + SSIM_C1;                                  \
        const float t4 = 0.5f * (M - U) + SSIM_C2;                            \
        ssum += __fdividef(t1 * t2, t3 * t4);                                 \
    }                                                                         \
} while (0)

// Guard-free phase (full blocks: ir < 176, fill row ir+3 <= 178 < nrows).
#define PHASEF(P, IRV) do {                                                   \
    const int irf_ = (IRV);                                                   \
    CPA_WAIT2();                                                              \
    const unsigned rbf_ = sbu + (unsigned)(irf_ & 7) * BSTRIDE;               \
    TRANS(rbf_);                                                              \
    if (tailst) TRANS(rbf_ + 256u);                                           \
    FILLF(irf_ + 3);                                                          \
    CPA_COMMIT();                                                             \
    __syncwarp();                                                             \
    ROWCOMP(P, irf_, rbf_);                                                   \
} while (0)

// Guarded tail phase (rows 176..nrows-1).
#define PHASET(P, IRV) do {                                                   \
    const int irt_ = (IRV);                                                   \
    if (irt_ < nrows) {                                                       \
        CPA_WAIT2();                                                          \
        const unsigned rbt_ = sbu + (unsigned)(irt_ & 7) * BSTRIDE;           \
        TRANS(rbt_);                                                          \
        if (tailst) TRANS(rbt_ + 256u);                                       \
        if (irt_ + 3 < nrows) FILLF(irt_ + 3);                                \
        CPA_COMMIT();                                                         \
        __syncwarp();                                                         \
        ROWCOMP(P, irt_, rbt_);                                               \
    }                                                                         \
} while (0)

__global__ void __launch_bounds__(NT, 1)
ssim_main(const float* __restrict__ img1, const float* __restrict__ img2,
          float* __restrict__ out)
{
    // Normalized 1D Gaussian, sigma=1.5, 11 taps
    const float W[11] = {
        0.00102838f, 0.00759874f, 0.03600077f, 0.10936069f, 0.21300553f,
        0.26601180f,
        0.21300553f, 0.10936069f, 0.03600077f, 0.00759874f, 0.00102838f
    };
    // Duplicated 64-bit weight pairs (w|w) for f32x2 ops (constant-folded)
    ull W2[11];
#pragma unroll
    for (int k = 0; k < 11; ++k) {
        const unsigned u = __float_as_uint(W[k]);
        W2[k] = ((ull)u << 32) | (ull)u;
    }

    const int band  = blockIdx.x;           // 0..2
    const int plane = blockIdx.y;           // 0..47
    const int t     = threadIdx.x;          // column 0..511
    const int l     = t & 31;               // lane
    const int w     = t >> 5;               // warp
    const int r0    = band * TH;
    const int rows  = (IMH - r0 < TH) ? (IMH - r0) : TH;   // 171/171/170
    const int nrows = rows + 10;            // 181/181/180
    const int pbase = plane * (IMW * IMH);

    // Warp-private 8-deep rotating halo segments.
    // Filled as (img1, img2) by cp.async; transformed in place to (S, D).
    __shared__ float2 seg[8][16][44];

    // Static ring (packed): slot s <-> output rows m with m % 11 == s.
    ull APQ[11], ASD[11];
#pragma unroll
    for (int j = 0; j < 11; ++j) { APQ[j] = 0ULL; ASD[j] = 0ULL; }

    // Column mapping:
    //   slot j = l      <-> col t - 5   (valid iff t >= 5)
    //   slot j = 32 + l <-> col t + 27  (exists iff l < 10, valid iff < 512)
    const bool mainok = (t >= 5);
    const bool tailst = (l < 10);
    const bool tailok = tailst && (t + 27 < IMW);

    // Base pointers for this lane's main column (col t-5), row gr=0.
    const float* bp1 = img1 + pbase + (t - 5);
    const float* bp2 = img2 + pbase + (t - 5);

    // u32 shared address of this warp+lane's slot in buffer 0
    unsigned sbu;
    asm("{ .reg .u64 tt; cvta.to.shared.u64 tt, %1; cvt.u32.u64 %0, tt; }"
        : "=r"(sbu) : "l"(&seg[0][w][l]));
    const unsigned BSTRIDE = 16u * 44u * 8u;   // bytes per buffer (5632)

    auto FILLF = [&](int rn) {
        const int gr = r0 - 5 + rn;             // global row (zero pad if OOB)
        const unsigned d = sbu + (unsigned)(rn & 7) * BSTRIDE;
        if ((unsigned)gr < (unsigned)IMH) {
            const float* p1 = bp1 + gr * IMW;   // one IMAD.WIDE each
            const float* p2 = bp2 + gr * IMW;
            if (mainok) { CPA4(d, p1);       CPA4(d + 4u, p2); }
            if (tailok) { CPA4T(d, p1);      CPA4T(d + 4u, p2); }
        } else {
            const float z = 0.f;
            asm volatile("st.shared.v2.f32 [%0], {%1,%1};" :: "r"(d), "f"(z));
            if (tailst)
                asm volatile("st.shared.v2.f32 [%0+256], {%1,%1};"
                             :: "r"(d), "f"(z));
        }
    };

    // Pre-zero slots never written by cp.async (col-invalid); all 8 buffers.
#pragma unroll
    for (int b = 0; b < 8; ++b) {
        if (!mainok)           seg[b][w][l]      = make_float2(0.f, 0.f);
        if (tailst && !tailok) seg[b][w][32 + l] = make_float2(0.f, 0.f);
    }

    // Prologue: rows 0,1,2 in flight as three groups.
    FILLF(0); CPA_COMMIT();
    FILLF(1); CPA_COMMIT();
    FILLF(2); CPA_COMMIT();
    __syncwarp();

    float ssum = 0.f;

    // 16 guard-free blocks: rows 0..175 (valid for nrows in {180,181};
    // fill rows reach 178 <= nrows-2).
#pragma unroll 1
    for (int base = 0; base < 176; base += 11) {
#pragma unroll
        for (int q = 0; q < 11; ++q) {
            PHASEF(q, base + q);
        }
    }
    // Guarded tail: rows 176..nrows-1 (176 % 11 == 0 -> P == q).
    {
#pragma unroll
        for (int q = 0; q < 11; ++q) {
            PHASET(q, 176 + q);
        }
    }

    // ---- deterministic block reduction ----
    __syncthreads();
#pragma unroll
    for (int off = 16; off; off >>= 1)
        ssum += __shfl_xor_sync(0xffffffffu, ssum, off);

    __shared__ float wsum[16];
    __shared__ bool  islast;
    if (l == 0) wsum[w] = ssum;
    __syncthreads();
    if (t == 0) {
        float v = 0.f;
#pragma unroll
        for (int i = 0; i < 16; ++i) v += wsum[i];
        g_partials[plane * NBANDS + band] = v;
        __threadfence();
        const unsigned n = atomicAdd(&g_count, 1u);
        islast = (n == (unsigned)(NBLOCKS - 1));
    }
    __syncthreads();

    // ---- last CTA: fixed-order (deterministic) final reduction ----
    if (islast) {
        __threadfence();
        float v = (t < NBLOCKS) ? g_partials[t] : 0.f;
#pragma unroll
        for (int off = 16; off; off >>= 1)
            v += __shfl_xor_sync(0xffffffffu, v, off);
        if (l == 0) wsum[w] = v;
        __syncthreads();
        if (t == 0) {
            float s = 0.f;
#pragma unroll
            for (int i = 0; i < 16; ++i) s += wsum[i];
            out[0] = s * (1.0f / 12582912.0f);  // / (16*3*512*512)
            g_count = 0u;                        // reset for next graph replay
        }
    }
}

extern "C" void kernel_launch(void* const* d_in, const int* in_sizes, int n_in,
                              void* d_out, int out_size)
{
    const float* img1 = (const float*)d_in[0];
    const float* img2 = (const float*)d_in[1];
    (void)in_sizes; (void)n_in; (void)out_size;

    dim3 grid(NBANDS, NPLANES);
    ssim_main<<<grid, NT>>>(img1, img2, (float*)d_out);
}